// round 14
// baseline (speedup 1.0000x reference)
#include <cuda_runtime.h>
#include <cuda_fp16.h>

#define NMAX 100352
#define THREADS 256
#define FULL 0xffffffffu

// ---- scratch (device globals; zero-initialized at module load) ----
// g_deg_* are re-zeroed inside k_prep each launch -> deterministic.
__device__ __align__(256) int    g_deg_s[NMAX];
__device__ __align__(256) int    g_deg_d[NMAX];
__device__ __align__(256) float  g_ns[NMAX];
__device__ __align__(256) float  g_nd[NMAX];
__device__ __align__(256) float  g_hx1[NMAX * 32];   // fp32: ns * (feat @ W1)
__device__ __align__(256) float  g_agg1[NMAX * 32];  // fp32 RED accumulator
__device__ __align__(256) __half g_h2x[NMAX * 16];   // fp16: (relu(.)*ns) @ W2

// K1: integer degree histogram (4 edges/thread)
__global__ void k_deg(const int* __restrict__ src, const int* __restrict__ dst, int e) {
    int t = blockIdx.x * blockDim.x + threadIdx.x;
    int base = t * 4;
    if (base + 3 < e) {
        int4 s4 = *(const int4*)(src + base);
        int4 d4 = *(const int4*)(dst + base);
        atomicAdd(&g_deg_s[s4.x], 1); atomicAdd(&g_deg_s[s4.y], 1);
        atomicAdd(&g_deg_s[s4.z], 1); atomicAdd(&g_deg_s[s4.w], 1);
        atomicAdd(&g_deg_d[d4.x], 1); atomicAdd(&g_deg_d[d4.y], 1);
        atomicAdd(&g_deg_d[d4.z], 1); atomicAdd(&g_deg_d[d4.w], 1);
    } else {
        for (int i = base; i < e; i++) {
            atomicAdd(&g_deg_s[src[i]], 1);
            atomicAdd(&g_deg_d[dst[i]], 1);
        }
    }
}

// K2: fused prep: zero agg1, out := b2, norms, re-zero degree tables
__global__ void k_prep(float* __restrict__ out, const float* __restrict__ b2, int n) {
    int t = blockIdx.x * blockDim.x + threadIdx.x;
    if (t < n * 8) ((float4*)g_agg1)[t] = make_float4(0.f, 0.f, 0.f, 0.f);
    if (t < n * 4) ((float4*)out)[t] = ((const float4*)b2)[t & 3];
    if (t < n) {
        g_ns[t] = rsqrtf(fmaxf((float)g_deg_s[t], 1.0f));
        g_nd[t] = rsqrtf(fmaxf((float)g_deg_d[t], 1.0f));
        g_deg_s[t] = 0;
        g_deg_d[t] = 0;
    }
}

// K3: xform1 (smem staged): g_hx1[n,:] = ns[n] * (feat[n,:] @ W1)   (fp32)
__global__ void __launch_bounds__(THREADS) k_xform1(const float* __restrict__ feat,
                                                    const float* __restrict__ W1, int n) {
    __shared__ float sf[256 * 33];
    int tid = threadIdx.x;
    int lane = tid & 31, w = tid >> 5;
    float w1[32];
#pragma unroll
    for (int k = 0; k < 32; k++) w1[k] = __ldg(W1 + k * 32 + lane);

    int base = blockIdx.x * 256;
    int cnt = min(256, n - base);
    for (int i = tid; i < cnt * 32; i += 256) {
        int node = i >> 5, col = i & 31;
        sf[node * 33 + col] = feat[(size_t)(base + node) * 32 + col];
    }
    __syncthreads();

    for (int t = 0; t < 32; t += 2) {
        int l0 = w * 32 + t, l1 = l0 + 1;
        if (l0 >= cnt) break;
        float acc0 = 0.f, acc1 = 0.f;
        const float* r0 = sf + l0 * 33;
        const float* r1 = sf + l1 * 33;
        bool has1 = (l1 < cnt);
#pragma unroll
        for (int k = 0; k < 32; k++) {
            acc0 = fmaf(r0[k], w1[k], acc0);
            acc1 = fmaf(r1[k], w1[k], acc1);
        }
        int n0 = base + l0;
        g_hx1[(size_t)n0 * 32 + lane] = acc0 * g_ns[n0];
        if (has1) g_hx1[(size_t)(n0 + 1) * 32 + lane] = acc1 * g_ns[n0 + 1];
    }
}

// K4: edge RED layer 1 (fp32, measured-best): 8 lanes/edge, one float4/lane,
// FOUR distant edges per thread (e0, e0+q, e0+2q, e0+3q).
__global__ void k_edge1(const int* __restrict__ src, const int* __restrict__ dst,
                        const float* __restrict__ ew, int e, int q) {
    int t = blockIdx.x * blockDim.x + threadIdx.x;
    if (t >= q * 8) return;
    int c4 = (t & 7) * 4;
    int e0 = t >> 3;

    int  eid[4];
    bool has[4];
#pragma unroll
    for (int u = 0; u < 4; u++) {
        eid[u] = e0 + u * q;
        has[u] = (eid[u] < e);
    }

    int s[4], d[4]; float wt[4];
#pragma unroll
    for (int u = 0; u < 4; u++) {
        s[u] = has[u] ? __ldg(src + eid[u]) : 0;
        d[u] = has[u] ? __ldg(dst + eid[u]) : 0;
        wt[u] = has[u] ? __ldg(ew + eid[u]) : 0.f;
    }

    float4 v[4];
#pragma unroll
    for (int u = 0; u < 4; u++) {
        v[u] = has[u] ? *(const float4*)(g_hx1 + (size_t)s[u] * 32 + c4)
                      : make_float4(0.f, 0.f, 0.f, 0.f);
        v[u].x *= wt[u]; v[u].y *= wt[u]; v[u].z *= wt[u]; v[u].w *= wt[u];
    }

#pragma unroll
    for (int u = 0; u < 4; u++) {
        if (has[u])
            asm volatile("red.global.add.v4.f32 [%0], {%1,%2,%3,%4};"
                         :: "l"(g_agg1 + (size_t)d[u] * 32 + c4),
                            "f"(v[u].x), "f"(v[u].y), "f"(v[u].z), "f"(v[u].w)
                         : "memory");
    }
}

// K5: xform2 (smem staged): h = relu(nd*agg + b1) * ns; g_h2x = half(h @ W2)
__global__ void __launch_bounds__(THREADS) k_xform2(const float* __restrict__ W2,
                                                    const float* __restrict__ b1, int n) {
    __shared__ float sf[256 * 33];
    __shared__ float sb1[32];
    int tid = threadIdx.x;
    int lane = tid & 31, w = tid >> 5;
    int p = lane >> 4, j = lane & 15;
    for (int i = tid; i < 32; i += 256) sb1[i] = __ldg(b1 + i);
    float w2[32];
#pragma unroll
    for (int k = 0; k < 32; k++) w2[k] = __ldg(W2 + k * 16 + j);
    __syncthreads();

    int base = blockIdx.x * 256;
    int cnt = min(256, n - base);
    for (int i = tid; i < cnt * 32; i += 256) {
        int node = i >> 5, col = i & 31;
        int gn = base + node;
        float a = g_agg1[(size_t)gn * 32 + col];
        sf[node * 33 + col] = fmaxf(fmaf(a, g_nd[gn], sb1[col]), 0.f) * g_ns[gn];
    }
    __syncthreads();

    for (int t = 0; t < 32; t += 2) {
        int l = w * 32 + t + p;
        if (l >= cnt) continue;
        float acc = 0.f;
        const float* r = sf + l * 33;
#pragma unroll
        for (int k = 0; k < 32; k++) acc = fmaf(r[k], w2[k], acc);
        g_h2x[(size_t)(base + l) * 16 + j] = __float2half_rn(acc);
    }
}

// K6: edge RED layer 2 (fp16 gather, measured-best): 4 lanes/edge, 4 halfs
// (8B) per lane, TWO distant edges/thread. nd[d] folded; out pre-inited to b2.
__global__ void k_edge2(const int* __restrict__ src, const int* __restrict__ dst,
                        const float* __restrict__ ew, float* __restrict__ out,
                        int e, int half) {
    int t = blockIdx.x * blockDim.x + threadIdx.x;
    if (t >= half * 4) return;
    int c = t & 3;
    int e0 = t >> 2;
    int e1 = e0 + half;
    bool has1 = (e1 < e);

    int s0 = __ldg(src + e0);
    int d0 = __ldg(dst + e0);
    float w0 = __ldg(ew + e0);
    int s1 = 0, d1 = 0; float w1 = 0.f;
    if (has1) {
        s1 = __ldg(src + e1);
        d1 = __ldg(dst + e1);
        w1 = __ldg(ew + e1);
    }
    w0 *= g_nd[d0];
    if (has1) w1 *= g_nd[d1];

    uint2 r0 = *(const uint2*)(g_h2x + (size_t)s0 * 16 + c * 4);
    uint2 r1 = has1 ? *(const uint2*)(g_h2x + (size_t)s1 * 16 + c * 4)
                    : make_uint2(0u, 0u);

    float2 p0a = __half22float2(*(__half2*)&r0.x);
    float2 p0b = __half22float2(*(__half2*)&r0.y);
    float2 p1a = __half22float2(*(__half2*)&r1.x);
    float2 p1b = __half22float2(*(__half2*)&r1.y);

    float4 v0 = make_float4(p0a.x * w0, p0a.y * w0, p0b.x * w0, p0b.y * w0);
    float4 v1 = make_float4(p1a.x * w1, p1a.y * w1, p1b.x * w1, p1b.y * w1);

    asm volatile("red.global.add.v4.f32 [%0], {%1,%2,%3,%4};"
                 :: "l"(out + (size_t)d0 * 16 + c * 4),
                    "f"(v0.x), "f"(v0.y), "f"(v0.z), "f"(v0.w) : "memory");
    if (has1)
        asm volatile("red.global.add.v4.f32 [%0], {%1,%2,%3,%4};"
                     :: "l"(out + (size_t)d1 * 16 + c * 4),
                        "f"(v1.x), "f"(v1.y), "f"(v1.z), "f"(v1.w) : "memory");
}

static inline int cdiv(long long a, int b) { return (int)((a + b - 1) / b); }

extern "C" void kernel_launch(void* const* d_in, const int* in_sizes, int n_in,
                              void* d_out, int out_size) {
    const float* feat = (const float*)d_in[0];
    const int*   src  = (const int*)d_in[1];
    const int*   dst  = (const int*)d_in[2];
    const float* ew   = (const float*)d_in[3];
    const float* W1   = (const float*)d_in[4];
    const float* b1   = (const float*)d_in[5];
    const float* W2   = (const float*)d_in[6];
    const float* b2   = (const float*)d_in[7];
    float* out = (float*)d_out;

    int n = in_sizes[0] / 32;
    int e = in_sizes[1];
    int q = (e + 3) / 4;        // 4-edges-per-thread stride (edge1)
    int half = (e + 1) / 2;     // 2-edges-per-thread stride (edge2)

    k_deg   <<<cdiv(cdiv(e, 4), THREADS), THREADS>>>(src, dst, e);
    k_prep  <<<cdiv((long long)n * 8, THREADS), THREADS>>>(out, b2, n);
    k_xform1<<<cdiv(n, 256), THREADS>>>(feat, W1, n);
    k_edge1 <<<cdiv((long long)q * 8, THREADS), THREADS>>>(src, dst, ew, e, q);
    k_xform2<<<cdiv(n, 256), THREADS>>>(W2, b1, n);
    k_edge2 <<<cdiv((long long)half * 4, THREADS), THREADS>>>(src, dst, ew, out, e, half);
}

// round 15
// speedup vs baseline: 1.0186x; 1.0186x over previous
#include <cuda_runtime.h>
#include <cuda_fp16.h>

#define NMAX 100352
#define THREADS 256
#define FULL 0xffffffffu

// ---- scratch (device globals; zero-initialized at module load) ----
// g_deg_* are re-zeroed inside k_xform1 each launch -> deterministic.
__device__ __align__(256) int    g_deg_s[NMAX];
__device__ __align__(256) int    g_deg_d[NMAX];
__device__ __align__(256) float  g_ns[NMAX];
__device__ __align__(256) float  g_nd[NMAX];
__device__ __align__(256) float  g_hx1[NMAX * 32];   // fp32: ns * (feat @ W1)
__device__ __align__(256) float  g_agg1[NMAX * 32];  // fp32 RED accumulator
__device__ __align__(256) __half g_h2x[NMAX * 16];   // fp16: (relu(.)*ns) @ W2

// K1: integer degree histogram (4 edges/thread)
__global__ void k_deg(const int* __restrict__ src, const int* __restrict__ dst, int e) {
    int t = blockIdx.x * blockDim.x + threadIdx.x;
    int base = t * 4;
    if (base + 3 < e) {
        int4 s4 = *(const int4*)(src + base);
        int4 d4 = *(const int4*)(dst + base);
        atomicAdd(&g_deg_s[s4.x], 1); atomicAdd(&g_deg_s[s4.y], 1);
        atomicAdd(&g_deg_s[s4.z], 1); atomicAdd(&g_deg_s[s4.w], 1);
        atomicAdd(&g_deg_d[d4.x], 1); atomicAdd(&g_deg_d[d4.y], 1);
        atomicAdd(&g_deg_d[d4.z], 1); atomicAdd(&g_deg_d[d4.w], 1);
    } else {
        for (int i = base; i < e; i++) {
            atomicAdd(&g_deg_s[src[i]], 1);
            atomicAdd(&g_deg_d[dst[i]], 1);
        }
    }
}

// K2: xform1 FUSED: norms from degrees (+ re-zero deg tables), zero agg1
// slice, then g_hx1[n,:] = ns[n] * (feat[n,:] @ W1)   (fp32)
__global__ void __launch_bounds__(THREADS) k_xform1(const float* __restrict__ feat,
                                                    const float* __restrict__ W1, int n) {
    __shared__ float sf[256 * 33];
    __shared__ float sns[256];
    int tid = threadIdx.x;
    int lane = tid & 31, w = tid >> 5;
    float w1[32];
#pragma unroll
    for (int k = 0; k < 32; k++) w1[k] = __ldg(W1 + k * 32 + lane);

    int base = blockIdx.x * 256;
    int cnt = min(256, n - base);

    // (a) norms for this block's nodes + re-zero degree tables
    if (tid < cnt) {
        int gn = base + tid;
        float ns = rsqrtf(fmaxf((float)g_deg_s[gn], 1.0f));
        float nd = rsqrtf(fmaxf((float)g_deg_d[gn], 1.0f));
        sns[tid] = ns;
        g_ns[gn] = ns;
        g_nd[gn] = nd;
        g_deg_s[gn] = 0;
        g_deg_d[gn] = 0;
    }

    // (b) zero this block's agg1 slice (cnt*32 floats = cnt*8 float4)
    {
        float4* az = (float4*)(g_agg1 + (size_t)base * 32);
        for (int i = tid; i < cnt * 8; i += 256)
            az[i] = make_float4(0.f, 0.f, 0.f, 0.f);
    }

    // (c) stage features
    for (int i = tid; i < cnt * 32; i += 256) {
        int node = i >> 5, col = i & 31;
        sf[node * 33 + col] = feat[(size_t)(base + node) * 32 + col];
    }
    __syncthreads();

    // (d) GEMM
    for (int t = 0; t < 32; t += 2) {
        int l0 = w * 32 + t, l1 = l0 + 1;
        if (l0 >= cnt) break;
        float acc0 = 0.f, acc1 = 0.f;
        const float* r0 = sf + l0 * 33;
        const float* r1 = sf + l1 * 33;
        bool has1 = (l1 < cnt);
#pragma unroll
        for (int k = 0; k < 32; k++) {
            acc0 = fmaf(r0[k], w1[k], acc0);
            acc1 = fmaf(r1[k], w1[k], acc1);
        }
        int n0 = base + l0;
        g_hx1[(size_t)n0 * 32 + lane] = acc0 * sns[l0];
        if (has1) g_hx1[(size_t)(n0 + 1) * 32 + lane] = acc1 * sns[l1];
    }
}

// K3: edge RED layer 1 (fp32): 8 lanes/edge, one float4/lane,
// FOUR distant edges per thread (e0, e0+q, e0+2q, e0+3q).
__global__ void k_edge1(const int* __restrict__ src, const int* __restrict__ dst,
                        const float* __restrict__ ew, int e, int q) {
    int t = blockIdx.x * blockDim.x + threadIdx.x;
    if (t >= q * 8) return;
    int c4 = (t & 7) * 4;
    int e0 = t >> 3;

    int  eid[4];
    bool has[4];
#pragma unroll
    for (int u = 0; u < 4; u++) {
        eid[u] = e0 + u * q;
        has[u] = (eid[u] < e);
    }

    int s[4], d[4]; float wt[4];
#pragma unroll
    for (int u = 0; u < 4; u++) {
        s[u] = has[u] ? __ldg(src + eid[u]) : 0;
        d[u] = has[u] ? __ldg(dst + eid[u]) : 0;
        wt[u] = has[u] ? __ldg(ew + eid[u]) : 0.f;
    }

    float4 v[4];
#pragma unroll
    for (int u = 0; u < 4; u++) {
        v[u] = has[u] ? *(const float4*)(g_hx1 + (size_t)s[u] * 32 + c4)
                      : make_float4(0.f, 0.f, 0.f, 0.f);
        v[u].x *= wt[u]; v[u].y *= wt[u]; v[u].z *= wt[u]; v[u].w *= wt[u];
    }

#pragma unroll
    for (int u = 0; u < 4; u++) {
        if (has[u])
            asm volatile("red.global.add.v4.f32 [%0], {%1,%2,%3,%4};"
                         :: "l"(g_agg1 + (size_t)d[u] * 32 + c4),
                            "f"(v[u].x), "f"(v[u].y), "f"(v[u].z), "f"(v[u].w)
                         : "memory");
    }
}

// K4: xform2 FUSED: out rows := b2 (runs before edge2), then
// h = relu(nd*agg + b1) * ns; g_h2x = half(h @ W2)
__global__ void __launch_bounds__(THREADS) k_xform2(const float* __restrict__ W2,
                                                    const float* __restrict__ b1,
                                                    const float* __restrict__ b2,
                                                    float* __restrict__ out, int n) {
    __shared__ float sf[256 * 33];
    __shared__ float sb1[32];
    int tid = threadIdx.x;
    int lane = tid & 31, w = tid >> 5;
    int p = lane >> 4, j = lane & 15;
    for (int i = tid; i < 32; i += 256) sb1[i] = __ldg(b1 + i);
    float w2[32];
#pragma unroll
    for (int k = 0; k < 32; k++) w2[k] = __ldg(W2 + k * 16 + j);

    int base = blockIdx.x * 256;
    int cnt = min(256, n - base);

    // (a) init this block's out rows to b2 (coalesced)
    {
        float* orow = out + (size_t)base * 16;
        for (int i = tid; i < cnt * 16; i += 256)
            orow[i] = __ldg(b2 + (i & 15));
    }

    // (b) stage h = relu(nd*agg + b1) * ns
    for (int i = tid; i < cnt * 32; i += 256) {
        int node = i >> 5, col = i & 31;
        int gn = base + node;
        float a = g_agg1[(size_t)gn * 32 + col];
        sf[node * 33 + col] = fmaxf(fmaf(a, g_nd[gn], sb1[col]), 0.f) * g_ns[gn];
    }
    __syncthreads();

    // (c) GEMM 32->16, write fp16
    for (int t = 0; t < 32; t += 2) {
        int l = w * 32 + t + p;
        if (l >= cnt) continue;
        float acc = 0.f;
        const float* r = sf + l * 33;
#pragma unroll
        for (int k = 0; k < 32; k++) acc = fmaf(r[k], w2[k], acc);
        g_h2x[(size_t)(base + l) * 16 + j] = __float2half_rn(acc);
    }
}

// K5: edge RED layer 2 (fp16 gather): 4 lanes/edge, 4 halfs (8B) per lane,
// TWO distant edges/thread. nd[d] folded; out pre-inited to b2 by xform2.
__global__ void k_edge2(const int* __restrict__ src, const int* __restrict__ dst,
                        const float* __restrict__ ew, float* __restrict__ out,
                        int e, int half) {
    int t = blockIdx.x * blockDim.x + threadIdx.x;
    if (t >= half * 4) return;
    int c = t & 3;
    int e0 = t >> 2;
    int e1 = e0 + half;
    bool has1 = (e1 < e);

    int s0 = __ldg(src + e0);
    int d0 = __ldg(dst + e0);
    float w0 = __ldg(ew + e0);
    int s1 = 0, d1 = 0; float w1 = 0.f;
    if (has1) {
        s1 = __ldg(src + e1);
        d1 = __ldg(dst + e1);
        w1 = __ldg(ew + e1);
    }
    w0 *= g_nd[d0];
    if (has1) w1 *= g_nd[d1];

    uint2 r0 = *(const uint2*)(g_h2x + (size_t)s0 * 16 + c * 4);
    uint2 r1 = has1 ? *(const uint2*)(g_h2x + (size_t)s1 * 16 + c * 4)
                    : make_uint2(0u, 0u);

    float2 p0a = __half22float2(*(__half2*)&r0.x);
    float2 p0b = __half22float2(*(__half2*)&r0.y);
    float2 p1a = __half22float2(*(__half2*)&r1.x);
    float2 p1b = __half22float2(*(__half2*)&r1.y);

    float4 v0 = make_float4(p0a.x * w0, p0a.y * w0, p0b.x * w0, p0b.y * w0);
    float4 v1 = make_float4(p1a.x * w1, p1a.y * w1, p1b.x * w1, p1b.y * w1);

    asm volatile("red.global.add.v4.f32 [%0], {%1,%2,%3,%4};"
                 :: "l"(out + (size_t)d0 * 16 + c * 4),
                    "f"(v0.x), "f"(v0.y), "f"(v0.z), "f"(v0.w) : "memory");
    if (has1)
        asm volatile("red.global.add.v4.f32 [%0], {%1,%2,%3,%4};"
                     :: "l"(out + (size_t)d1 * 16 + c * 4),
                        "f"(v1.x), "f"(v1.y), "f"(v1.z), "f"(v1.w) : "memory");
}

static inline int cdiv(long long a, int b) { return (int)((a + b - 1) / b); }

extern "C" void kernel_launch(void* const* d_in, const int* in_sizes, int n_in,
                              void* d_out, int out_size) {
    const float* feat = (const float*)d_in[0];
    const int*   src  = (const int*)d_in[1];
    const int*   dst  = (const int*)d_in[2];
    const float* ew   = (const float*)d_in[3];
    const float* W1   = (const float*)d_in[4];
    const float* b1   = (const float*)d_in[5];
    const float* W2   = (const float*)d_in[6];
    const float* b2   = (const float*)d_in[7];
    float* out = (float*)d_out;

    int n = in_sizes[0] / 32;
    int e = in_sizes[1];
    int q = (e + 3) / 4;        // 4-edges-per-thread stride (edge1)
    int half = (e + 1) / 2;     // 2-edges-per-thread stride (edge2)

    k_deg   <<<cdiv(cdiv(e, 4), THREADS), THREADS>>>(src, dst, e);
    k_xform1<<<cdiv(n, 256), THREADS>>>(feat, W1, n);
    k_edge1 <<<cdiv((long long)q * 8, THREADS), THREADS>>>(src, dst, ew, e, q);
    k_xform2<<<cdiv(n, 256), THREADS>>>(W2, b1, b2, out, n);
    k_edge2 <<<cdiv((long long)half * 4, THREADS), THREADS>>>(src, dst, ew, out, e, half);
}

// round 17
// speedup vs baseline: 1.0717x; 1.0521x over previous
#include <cuda_runtime.h>
#include <cuda_fp16.h>

#define NMAX 100352
#define THREADS 256
#define NB 128                 // nodes per xform block
#define FULL 0xffffffffu

// ---- scratch (device globals; zero-initialized at module load) ----
// g_deg_* are re-zeroed inside k_xform1 each launch -> deterministic.
__device__ __align__(256) int    g_deg_s[NMAX];
__device__ __align__(256) int    g_deg_d[NMAX];
__device__ __align__(256) float  g_ns[NMAX];
__device__ __align__(256) float  g_nd[NMAX];
__device__ __align__(256) float  g_hx1[NMAX * 32];   // fp32: ns * (feat @ W1)
__device__ __align__(256) float  g_agg1[NMAX * 32];  // fp32 RED accumulator
__device__ __align__(256) __half g_h2x[NMAX * 16];   // fp16: (relu(.)*ns) @ W2

// K1: integer degree histogram (4 edges/thread)
__global__ void k_deg(const int* __restrict__ src, const int* __restrict__ dst, int e) {
    int t = blockIdx.x * blockDim.x + threadIdx.x;
    int base = t * 4;
    if (base + 3 < e) {
        int4 s4 = *(const int4*)(src + base);
        int4 d4 = *(const int4*)(dst + base);
        atomicAdd(&g_deg_s[s4.x], 1); atomicAdd(&g_deg_s[s4.y], 1);
        atomicAdd(&g_deg_s[s4.z], 1); atomicAdd(&g_deg_s[s4.w], 1);
        atomicAdd(&g_deg_d[d4.x], 1); atomicAdd(&g_deg_d[d4.y], 1);
        atomicAdd(&g_deg_d[d4.z], 1); atomicAdd(&g_deg_d[d4.w], 1);
    } else {
        for (int i = base; i < e; i++) {
            atomicAdd(&g_deg_s[src[i]], 1);
            atomicAdd(&g_deg_d[dst[i]], 1);
        }
    }
}

// K2: xform1 FUSED: norms (+ re-zero deg tables), zero agg1 slice, then
// g_hx1[n,:] = ns[n] * (feat[n,:] @ W1).  NB=128 nodes/block, 8 warps.
__global__ void __launch_bounds__(THREADS) k_xform1(const float* __restrict__ feat,
                                                    const float* __restrict__ W1, int n) {
    __shared__ float sf[NB * 33];
    __shared__ float sns[NB];
    int tid = threadIdx.x;
    int lane = tid & 31, w = tid >> 5;
    float w1[32];
#pragma unroll
    for (int k = 0; k < 32; k++) w1[k] = __ldg(W1 + k * 32 + lane);

    int base = blockIdx.x * NB;
    int cnt = min(NB, n - base);

    // (a) norms for this block's nodes + re-zero degree tables
    if (tid < cnt) {
        int gn = base + tid;
        float ns = rsqrtf(fmaxf((float)g_deg_s[gn], 1.0f));
        float nd = rsqrtf(fmaxf((float)g_deg_d[gn], 1.0f));
        sns[tid] = ns;
        g_ns[gn] = ns;
        g_nd[gn] = nd;
        g_deg_s[gn] = 0;
        g_deg_d[gn] = 0;
    }

    // (b) zero this block's agg1 slice (cnt*32 floats = cnt*8 float4)
    {
        float4* az = (float4*)(g_agg1 + (size_t)base * 32);
        for (int i = tid; i < cnt * 8; i += THREADS)
            az[i] = make_float4(0.f, 0.f, 0.f, 0.f);
    }

    // (c) stage features
    for (int i = tid; i < cnt * 32; i += THREADS) {
        int node = i >> 5, col = i & 31;
        sf[node * 33 + col] = feat[(size_t)(base + node) * 32 + col];
    }
    __syncthreads();

    // (d) GEMM: warp w covers nodes [w*16, w*16+16)
    int w16 = w * 16;
#pragma unroll
    for (int t = 0; t < 16; t += 2) {
        int l0 = w16 + t, l1 = l0 + 1;
        if (l0 >= cnt) break;
        float acc0 = 0.f, acc1 = 0.f;
        const float* r0 = sf + l0 * 33;
        const float* r1 = sf + l1 * 33;
        bool has1 = (l1 < cnt);
#pragma unroll
        for (int k = 0; k < 32; k++) {
            acc0 = fmaf(r0[k], w1[k], acc0);
            acc1 = fmaf(r1[k], w1[k], acc1);
        }
        int n0 = base + l0;
        g_hx1[(size_t)n0 * 32 + lane] = acc0 * sns[l0];
        if (has1) g_hx1[(size_t)(n0 + 1) * 32 + lane] = acc1 * sns[l1];
    }
}

// K3: edge RED layer 1 (fp32): 8 lanes/edge, one float4/lane,
// FOUR distant edges per thread (e0, e0+q, e0+2q, e0+3q).
__global__ void k_edge1(const int* __restrict__ src, const int* __restrict__ dst,
                        const float* __restrict__ ew, int e, int q) {
    int t = blockIdx.x * blockDim.x + threadIdx.x;
    if (t >= q * 8) return;
    int c4 = (t & 7) * 4;
    int e0 = t >> 3;

    int  eid[4];
    bool has[4];
#pragma unroll
    for (int u = 0; u < 4; u++) {
        eid[u] = e0 + u * q;
        has[u] = (eid[u] < e);
    }

    int s[4], d[4]; float wt[4];
#pragma unroll
    for (int u = 0; u < 4; u++) {
        s[u] = has[u] ? __ldg(src + eid[u]) : 0;
        d[u] = has[u] ? __ldg(dst + eid[u]) : 0;
        wt[u] = has[u] ? __ldg(ew + eid[u]) : 0.f;
    }

    float4 v[4];
#pragma unroll
    for (int u = 0; u < 4; u++) {
        v[u] = has[u] ? *(const float4*)(g_hx1 + (size_t)s[u] * 32 + c4)
                      : make_float4(0.f, 0.f, 0.f, 0.f);
        v[u].x *= wt[u]; v[u].y *= wt[u]; v[u].z *= wt[u]; v[u].w *= wt[u];
    }

#pragma unroll
    for (int u = 0; u < 4; u++) {
        if (has[u])
            asm volatile("red.global.add.v4.f32 [%0], {%1,%2,%3,%4};"
                         :: "l"(g_agg1 + (size_t)d[u] * 32 + c4),
                            "f"(v[u].x), "f"(v[u].y), "f"(v[u].z), "f"(v[u].w)
                         : "memory");
    }
}

// K4: xform2 FUSED: out rows := b2, then h = relu(nd*agg + b1) * ns;
// g_h2x = half(h @ W2). NB=128 nodes/block; warp covers 16 nodes; each
// thread runs TWO independent chains (nodes la and la+8) per iteration.
__global__ void __launch_bounds__(THREADS) k_xform2(const float* __restrict__ W2,
                                                    const float* __restrict__ b1,
                                                    const float* __restrict__ b2,
                                                    float* __restrict__ out, int n) {
    __shared__ float sf[NB * 33];
    __shared__ float sb1[32];
    int tid = threadIdx.x;
    int lane = tid & 31, w = tid >> 5;
    int p = lane >> 4, j = lane & 15;
    for (int i = tid; i < 32; i += THREADS) sb1[i] = __ldg(b1 + i);
    float w2[32];
#pragma unroll
    for (int k = 0; k < 32; k++) w2[k] = __ldg(W2 + k * 16 + j);
    // FIX (R16 bug): sb1 is written by warp 0 only but read by ALL warps in
    // phase (b) below -> must synchronize before any thread reads it.
    __syncthreads();

    int base = blockIdx.x * NB;
    int cnt = min(NB, n - base);

    // (a) init this block's out rows to b2 (coalesced)
    {
        float* orow = out + (size_t)base * 16;
        for (int i = tid; i < cnt * 16; i += THREADS)
            orow[i] = __ldg(b2 + (i & 15));
    }

    // (b) stage h = relu(nd*agg + b1) * ns
    for (int i = tid; i < cnt * 32; i += THREADS) {
        int node = i >> 5, col = i & 31;
        int gn = base + node;
        float a = g_agg1[(size_t)gn * 32 + col];
        sf[node * 33 + col] = fmaxf(fmaf(a, g_nd[gn], sb1[col]), 0.f) * g_ns[gn];
    }
    __syncthreads();

    // (c) GEMM 32->16: warp w covers nodes [w*16, w*16+16).
    // Per iteration: node la = w*16 + t + p (half-warp p), and lb = la + 8.
    int w16 = w * 16;
#pragma unroll
    for (int t = 0; t < 8; t += 2) {
        int la = w16 + t + p;
        int lb = la + 8;
        float acca = 0.f, accb = 0.f;
        const float* ra = sf + la * 33;
        const float* rb = sf + lb * 33;
#pragma unroll
        for (int k = 0; k < 32; k++) {
            acca = fmaf(ra[k], w2[k], acca);
            accb = fmaf(rb[k], w2[k], accb);
        }
        if (la < cnt) g_h2x[(size_t)(base + la) * 16 + j] = __float2half_rn(acca);
        if (lb < cnt) g_h2x[(size_t)(base + lb) * 16 + j] = __float2half_rn(accb);
    }
}

// K5: edge RED layer 2 (fp16 gather): 4 lanes/edge, 4 halfs (8B) per lane,
// TWO distant edges/thread. nd[d] folded; out pre-inited to b2 by xform2.
__global__ void k_edge2(const int* __restrict__ src, const int* __restrict__ dst,
                        const float* __restrict__ ew, float* __restrict__ out,
                        int e, int half) {
    int t = blockIdx.x * blockDim.x + threadIdx.x;
    if (t >= half * 4) return;
    int c = t & 3;
    int e0 = t >> 2;
    int e1 = e0 + half;
    bool has1 = (e1 < e);

    int s0 = __ldg(src + e0);
    int d0 = __ldg(dst + e0);
    float w0 = __ldg(ew + e0);
    int s1 = 0, d1 = 0; float w1 = 0.f;
    if (has1) {
        s1 = __ldg(src + e1);
        d1 = __ldg(dst + e1);
        w1 = __ldg(ew + e1);
    }
    w0 *= g_nd[d0];
    if (has1) w1 *= g_nd[d1];

    uint2 r0 = *(const uint2*)(g_h2x + (size_t)s0 * 16 + c * 4);
    uint2 r1 = has1 ? *(const uint2*)(g_h2x + (size_t)s1 * 16 + c * 4)
                    : make_uint2(0u, 0u);

    float2 p0a = __half22float2(*(__half2*)&r0.x);
    float2 p0b = __half22float2(*(__half2*)&r0.y);
    float2 p1a = __half22float2(*(__half2*)&r1.x);
    float2 p1b = __half22float2(*(__half2*)&r1.y);

    float4 v0 = make_float4(p0a.x * w0, p0a.y * w0, p0b.x * w0, p0b.y * w0);
    float4 v1 = make_float4(p1a.x * w1, p1a.y * w1, p1b.x * w1, p1b.y * w1);

    asm volatile("red.global.add.v4.f32 [%0], {%1,%2,%3,%4};"
                 :: "l"(out + (size_t)d0 * 16 + c * 4),
                    "f"(v0.x), "f"(v0.y), "f"(v0.z), "f"(v0.w) : "memory");
    if (has1)
        asm volatile("red.global.add.v4.f32 [%0], {%1,%2,%3,%4};"
                     :: "l"(out + (size_t)d1 * 16 + c * 4),
                        "f"(v1.x), "f"(v1.y), "f"(v1.z), "f"(v1.w) : "memory");
}

static inline int cdiv(long long a, int b) { return (int)((a + b - 1) / b); }

extern "C" void kernel_launch(void* const* d_in, const int* in_sizes, int n_in,
                              void* d_out, int out_size) {
    const float* feat = (const float*)d_in[0];
    const int*   src  = (const int*)d_in[1];
    const int*   dst  = (const int*)d_in[2];
    const float* ew   = (const float*)d_in[3];
    const float* W1   = (const float*)d_in[4];
    const float* b1   = (const float*)d_in[5];
    const float* W2   = (const float*)d_in[6];
    const float* b2   = (const float*)d_in[7];
    float* out = (float*)d_out;

    int n = in_sizes[0] / 32;
    int e = in_sizes[1];
    int q = (e + 3) / 4;        // 4-edges-per-thread stride (edge1)
    int half = (e + 1) / 2;     // 2-edges-per-thread stride (edge2)

    k_deg   <<<cdiv(cdiv(e, 4), THREADS), THREADS>>>(src, dst, e);
    k_xform1<<<cdiv(n, NB), THREADS>>>(feat, W1, n);
    k_edge1 <<<cdiv((long long)q * 8, THREADS), THREADS>>>(src, dst, ew, e, q);
    k_xform2<<<cdiv(n, NB), THREADS>>>(W2, b1, b2, out, n);
    k_edge2 <<<cdiv((long long)half * 4, THREADS), THREADS>>>(src, dst, ew, out, e, half);
}